// round 2
// baseline (speedup 1.0000x reference)
#include <cuda_runtime.h>
#include <cstdint>

// Problem dims (fixed by the dataset)
#define M_TOK 4096      // B2*T tokens
#define K_DIM 4096      // hidden
#define V_DIM 32000     // vocab
#define T_SEQ 512
#define B2_   8
#define BH_   4         // B2/2
#define IGNORE_INDEX (-100)
#define BETA  0.1
#define ALPHA 1.0

// GEMM tiling
#define BM 64
#define BN 64
#define BK 32
#define NVB (V_DIM / BN)   // 500 vocab tiles

// Scratch (static device globals; no runtime allocation)
__device__ float g_partialM[(size_t)M_TOK * NVB];   // per (token, vtile) max
__device__ float g_partialS[(size_t)M_TOK * NVB];   // per (token, vtile) sum exp(v - max)
__device__ float g_labelLogit[M_TOK];
__device__ float g_logp[M_TOK];

// ---------------------------------------------------------------------------
// Kernel 1: tiled fp32 GEMM (logits tile) fused with per-tile logsumexp
// partials + label-logit gather. Grid: (V/BN, M/BM), 256 threads.
// NOTE: y is int32 (JAX x64 disabled canonicalizes int64 -> int32).
// ---------------------------------------------------------------------------
__global__ __launch_bounds__(256)
void gemm_lse_kernel(const float* __restrict__ X,
                     const float* __restrict__ W,
                     const int* __restrict__ Y)
{
    __shared__ float As[BK][BM];       // [k][token-row]
    __shared__ float Bs[BK][BN];       // [k][vocab-col]
    __shared__ float red[BM][17];      // padded reduction scratch
    __shared__ float rowMax[BM];

    const int tid   = threadIdx.x;
    const int tx    = tid & 15;        // 0..15 (vocab micro)
    const int ty    = tid >> 4;        // 0..15 (token micro)
    const int nBase = blockIdx.x * BN;
    const int mBase = blockIdx.y * BM;

    const float* Xg = X + (size_t)mBase * K_DIM;
    const float* Wg = W + (size_t)nBase * K_DIM;

    const int lr = tid >> 3;           // 0..31 : row within half-tile
    const int lc = (tid & 7) * 4;      // 0..28 : k offset (float4)

    float acc[4][4];
#pragma unroll
    for (int i = 0; i < 4; i++)
#pragma unroll
        for (int j = 0; j < 4; j++) acc[i][j] = 0.0f;

    for (int k0 = 0; k0 < K_DIM; k0 += BK) {
#pragma unroll
        for (int h = 0; h < 2; h++) {
            const int row = lr + h * 32;
            float4 a = *(const float4*)(Xg + (size_t)row * K_DIM + k0 + lc);
            As[lc + 0][row] = a.x; As[lc + 1][row] = a.y;
            As[lc + 2][row] = a.z; As[lc + 3][row] = a.w;
            float4 b = *(const float4*)(Wg + (size_t)row * K_DIM + k0 + lc);
            Bs[lc + 0][row] = b.x; Bs[lc + 1][row] = b.y;
            Bs[lc + 2][row] = b.z; Bs[lc + 3][row] = b.w;
        }
        __syncthreads();

#pragma unroll
        for (int k = 0; k < BK; k++) {
            const float4 a4 = *(const float4*)(&As[k][ty * 4]);
            const float4 b4 = *(const float4*)(&Bs[k][tx * 4]);
            const float av[4] = {a4.x, a4.y, a4.z, a4.w};
            const float bv[4] = {b4.x, b4.y, b4.z, b4.w};
#pragma unroll
            for (int i = 0; i < 4; i++)
#pragma unroll
                for (int j = 0; j < 4; j++)
                    acc[i][j] = fmaf(av[i], bv[j], acc[i][j]);
        }
        __syncthreads();
    }

    // ---- epilogue: per-row (token) max over this BN-wide vocab tile ----
#pragma unroll
    for (int i = 0; i < 4; i++) {
        float mx = fmaxf(fmaxf(acc[i][0], acc[i][1]), fmaxf(acc[i][2], acc[i][3]));
        red[ty * 4 + i][tx] = mx;
    }
    __syncthreads();
    if (tid < BM) {
        float mx = -3.4e38f;
#pragma unroll
        for (int j = 0; j < 16; j++) mx = fmaxf(mx, red[tid][j]);
        rowMax[tid] = mx;
    }
    __syncthreads();

    // per-row sum of exp(v - rowMax)
#pragma unroll
    for (int i = 0; i < 4; i++) {
        const float m = rowMax[ty * 4 + i];
        float s = 0.0f;
#pragma unroll
        for (int j = 0; j < 4; j++) s += __expf(acc[i][j] - m);
        red[ty * 4 + i][tx] = s;
    }
    __syncthreads();
    if (tid < BM) {
        float s = 0.0f;
#pragma unroll
        for (int j = 0; j < 16; j++) s += red[tid][j];
        const size_t token = (size_t)(mBase + tid);
        g_partialM[token * NVB + blockIdx.x] = rowMax[tid];
        g_partialS[token * NVB + blockIdx.x] = s;
    }

    // ---- label logit gather (exactly one thread in the whole grid matches) ----
#pragma unroll
    for (int i = 0; i < 4; i++) {
        const int token = mBase + ty * 4 + i;
        const int yv = Y[token];
#pragma unroll
        for (int j = 0; j < 4; j++) {
            if (yv == nBase + tx * 4 + j)
                g_labelLogit[token] = acc[i][j];
        }
    }
}

// ---------------------------------------------------------------------------
// Kernel 2: merge NVB partials per token -> per-token logp (masked => 0)
// ---------------------------------------------------------------------------
__global__ __launch_bounds__(128)
void lse_merge_kernel(const int* __restrict__ Y)
{
    const int token = blockIdx.x;
    const int tid   = threadIdx.x;
    __shared__ float sm[128];

    const float* pm = g_partialM + (size_t)token * NVB;
    const float* ps = g_partialS + (size_t)token * NVB;

    float mx = -3.4e38f;
    for (int i = tid; i < NVB; i += 128) mx = fmaxf(mx, pm[i]);
    sm[tid] = mx; __syncthreads();
    for (int s = 64; s > 0; s >>= 1) {
        if (tid < s) sm[tid] = fmaxf(sm[tid], sm[tid + s]);
        __syncthreads();
    }
    const float gm = sm[0];
    __syncthreads();

    float ssum = 0.0f;
    for (int i = tid; i < NVB; i += 128) ssum += ps[i] * __expf(pm[i] - gm);
    sm[tid] = ssum; __syncthreads();
    for (int s = 64; s > 0; s >>= 1) {
        if (tid < s) sm[tid] += sm[tid + s];
        __syncthreads();
    }

    if (tid == 0) {
        const float lse = gm + logf(sm[0]);
        const int yv = Y[token];
        g_logp[token] = (yv == IGNORE_INDEX) ? 0.0f : (g_labelLogit[token] - lse);
    }
}

// ---------------------------------------------------------------------------
// Kernel 3: per-sequence sums, NLL, CPO pairwise loss -> scalar
// ---------------------------------------------------------------------------
__global__ __launch_bounds__(512)
void final_kernel(const int* __restrict__ Y, float* __restrict__ out,
                  int out_size)
{
    const int tid = threadIdx.x;
    __shared__ double sm[512];
    __shared__ double allv[B2_];

    for (int s = 0; s < B2_; s++) {
        sm[tid] = (double)g_logp[s * T_SEQ + tid];
        __syncthreads();
        for (int st = 256; st > 0; st >>= 1) {
            if (tid < st) sm[tid] += sm[tid + st];
            __syncthreads();
        }
        if (tid == 0) allv[s] = sm[0];
        __syncthreads();
    }

    // mask count over chosen half
    int c = 0;
    for (int s = 0; s < BH_; s++) c += (Y[s * T_SEQ + tid] != IGNORE_INDEX) ? 1 : 0;
    sm[tid] = (double)c;
    __syncthreads();
    for (int st = 256; st > 0; st >>= 1) {
        if (tid < st) sm[tid] += sm[tid + st];
        __syncthreads();
    }

    // zero any extra output elements
    for (int i = tid; i < out_size; i += 512) out[i] = 0.0f;

    if (tid == 0) {
        const double cnt = sm[0];
        const double nll = -(allv[0] + allv[1] + allv[2] + allv[3]) / cnt;
        double lsum = 0.0;
        for (int b = 0; b < BH_; b++) {
            const double d = allv[b] - allv[BH_ + b];
            const double z = BETA * d;
            // log_sigmoid(z), numerically stable
            const double lsg = (z < 0.0) ? (z - log1p(exp(z))) : (-log1p(exp(-z)));
            lsum += -lsg;   // label_smoothing = 0
        }
        const double loss = nll * ALPHA + lsum / (double)BH_;
        out[0] = (float)loss;
    }
}

// ---------------------------------------------------------------------------
extern "C" void kernel_launch(void* const* d_in, const int* in_sizes, int n_in,
                              void* d_out, int out_size)
{
    const float* X = (const float*)d_in[0];   // (8,512,4096) f32
    const int*   Y = (const int*)d_in[1];     // (8,512) int32 (JAX canonicalized)
    const float* W = (const float*)d_in[2];   // (32000,4096) f32

    dim3 grid(V_DIM / BN, M_TOK / BM);   // (500, 64)
    gemm_lse_kernel<<<grid, 256>>>(X, W, Y);
    lse_merge_kernel<<<M_TOK, 128>>>(Y);
    final_kernel<<<1, 512>>>(Y, (float*)d_out, out_size);
}

// round 4
// speedup vs baseline: 6.3436x; 6.3436x over previous
#include <cuda_runtime.h>
#include <cstdint>

// ---------------------------------------------------------------- problem dims
#define M_TOK 4096
#define K_DIM 4096
#define V_DIM 32000
#define T_SEQ 512
#define B2_   8
#define BH_   4
#define IGNORE_INDEX (-100)
#define BETA  0.1
#define ALPHA 1.0

// ---------------------------------------------------------------- GEMM tiling
#define BM 128
#define BN 128
#define BK 32
#define BKP 36                    // padded k-stride (floats): conflict-free
#define NCHUNK (K_DIM / BK)       // 128
#define NVB (V_DIM / BN)          // 250
#define NMB (M_TOK / BM)          // 32
#define STAGE_FLOATS (BM * BKP)   // per-tensor per-stage
#define SMEM_DYN (4 * STAGE_FLOATS * 4)   // 2 stages x (A+B) x 4B = 73728

// ---------------------------------------------------------------- scratch
__device__ float g_partialM[(size_t)M_TOK * NVB];
__device__ float g_partialS[(size_t)M_TOK * NVB];
__device__ float g_labelLogit[M_TOK];
__device__ float g_logp[M_TOK];

// ---------------------------------------------------------------- helpers
__device__ __forceinline__ uint32_t smem_u32(const void* p) {
    return (uint32_t)__cvta_generic_to_shared(p);
}
__device__ __forceinline__ void cp16(uint32_t dst, const void* src) {
    asm volatile("cp.async.cg.shared.global [%0], [%1], 16;\n" :: "r"(dst), "l"(src));
}
__device__ __forceinline__ void cp_commit() {
    asm volatile("cp.async.commit_group;\n" ::: "memory");
}
template<int N> __device__ __forceinline__ void cp_wait() {
    asm volatile("cp.async.wait_group %0;\n" :: "n"(N) : "memory");
}
__device__ __forceinline__ void mma_tf32(float* c, const uint32_t* a, const uint32_t* b) {
    asm volatile(
        "mma.sync.aligned.m16n8k8.row.col.f32.tf32.tf32.f32 "
        "{%0,%1,%2,%3}, {%4,%5,%6,%7}, {%8,%9}, {%0,%1,%2,%3};"
        : "+f"(c[0]), "+f"(c[1]), "+f"(c[2]), "+f"(c[3])
        : "r"(a[0]), "r"(a[1]), "r"(a[2]), "r"(a[3]), "r"(b[0]), "r"(b[1]));
}

// ---------------------------------------------------------------------------
// Kernel 1: tf32 mma.sync GEMM (128x128 tile) + fused per-tile logsumexp
// partials + label-logit gather. grid=(32,250), 256 threads (8 warps 2x4).
// ---------------------------------------------------------------------------
__global__ void __launch_bounds__(256, 2)
gemm_lse_mma(const float* __restrict__ X, const float* __restrict__ W,
             const int* __restrict__ Y)
{
    extern __shared__ float smem[];
    float* sA = smem;                       // [2][BM][BKP]
    float* sB = smem + 2 * STAGE_FLOATS;    // [2][BN][BKP]
    __shared__ float s_red[BM][5];
    __shared__ float s_rowmax[BM];

    const int tid   = threadIdx.x;
    const int lane  = tid & 31;
    const int wid   = tid >> 5;
    const int wm    = wid & 1;      // 0..1 -> 64 rows
    const int wn    = wid >> 1;     // 0..3 -> 32 cols
    const int quad  = lane & 3;
    const int l4    = lane >> 2;
    const int mBase = blockIdx.x * BM;
    const int nBase = blockIdx.y * BN;

    const uint32_t sA_b = smem_u32(sA);
    const uint32_t sB_b = smem_u32(sB);

    // ------------- chunk loader (cp.async), 16B per op, 4 ops per tensor ----
    auto load_chunk = [&](int j, int stage) {
        const int k0 = j * BK;
#pragma unroll
        for (int q = 0; q < 4; q++) {
            const int idx = q * 256 + tid;
            const int row = idx >> 3, c = idx & 7;
            cp16(sA_b + (uint32_t)(((stage * BM + row) * BKP + c * 4) * 4),
                 X + (size_t)(mBase + row) * K_DIM + k0 + c * 4);
            cp16(sB_b + (uint32_t)(((stage * BN + row) * BKP + c * 4) * 4),
                 W + (size_t)(nBase + row) * K_DIM + k0 + c * 4);
        }
        cp_commit();
    };

    float acc[4][4][4];
#pragma unroll
    for (int mf = 0; mf < 4; mf++)
#pragma unroll
        for (int nf = 0; nf < 4; nf++)
#pragma unroll
            for (int r = 0; r < 4; r++) acc[mf][nf][r] = 0.0f;

    load_chunk(0, 0);
    load_chunk(1, 1);

    for (int i = 0; i < NCHUNK; i++) {
        if (i == NCHUNK - 1) cp_wait<0>(); else cp_wait<1>();
        __syncthreads();

        const int st = i & 1;
        const uint32_t* A = (const uint32_t*)(sA + st * STAGE_FLOATS);
        const uint32_t* B = (const uint32_t*)(sB + st * STAGE_FLOATS);

#pragma unroll
        for (int ks = 0; ks < 4; ks++) {
            const int kc = ks * 8 + quad;
            uint32_t a[4][4], b[4][2];
#pragma unroll
            for (int mf = 0; mf < 4; mf++) {
                const uint32_t* ap = A + (wm * 64 + mf * 16 + l4) * BKP + kc;
                a[mf][0] = ap[0];
                a[mf][1] = ap[8 * BKP];
                a[mf][2] = ap[4];
                a[mf][3] = ap[8 * BKP + 4];
            }
#pragma unroll
            for (int nf = 0; nf < 4; nf++) {
                const uint32_t* bp = B + (wn * 32 + nf * 8 + l4) * BKP + kc;
                b[nf][0] = bp[0];
                b[nf][1] = bp[4];
            }
#pragma unroll
            for (int mf = 0; mf < 4; mf++)
#pragma unroll
                for (int nf = 0; nf < 4; nf++)
                    mma_tf32(acc[mf][nf], a[mf], b[nf]);
        }
        __syncthreads();
        if (i + 2 < NCHUNK) load_chunk(i + 2, st);
    }

    // --------------------------- epilogue ----------------------------------
    // pass 1: per-row max over this 128-col tile
#pragma unroll
    for (int mf = 0; mf < 4; mf++) {
        float m0 = -3.4e38f, m1 = -3.4e38f;
#pragma unroll
        for (int nf = 0; nf < 4; nf++) {
            m0 = fmaxf(m0, fmaxf(acc[mf][nf][0], acc[mf][nf][1]));
            m1 = fmaxf(m1, fmaxf(acc[mf][nf][2], acc[mf][nf][3]));
        }
        m0 = fmaxf(m0, __shfl_xor_sync(0xffffffffu, m0, 1));
        m0 = fmaxf(m0, __shfl_xor_sync(0xffffffffu, m0, 2));
        m1 = fmaxf(m1, __shfl_xor_sync(0xffffffffu, m1, 1));
        m1 = fmaxf(m1, __shfl_xor_sync(0xffffffffu, m1, 2));
        if (quad == 0) {
            s_red[wm * 64 + mf * 16 + l4][wn]     = m0;
            s_red[wm * 64 + mf * 16 + l4 + 8][wn] = m1;
        }
    }
    __syncthreads();
    if (tid < BM) {
        const float rm = fmaxf(fmaxf(s_red[tid][0], s_red[tid][1]),
                               fmaxf(s_red[tid][2], s_red[tid][3]));
        s_rowmax[tid] = rm;
        g_partialM[(size_t)(mBase + tid) * NVB + blockIdx.y] = rm;
    }
    __syncthreads();

    // pass 2: per-row sum of exp(v - rowmax) + label gather
#pragma unroll
    for (int mf = 0; mf < 4; mf++) {
        const int r0 = wm * 64 + mf * 16 + l4;
        const int r1 = r0 + 8;
        const float c0 = s_rowmax[r0];
        const float c1 = s_rowmax[r1];
        const int y0 = Y[mBase + r0];
        const int y1 = Y[mBase + r1];
        float s0 = 0.0f, s1 = 0.0f;
#pragma unroll
        for (int nf = 0; nf < 4; nf++) {
            const int colg = nBase + wn * 32 + nf * 8 + 2 * quad;
            const float v0 = acc[mf][nf][0];
            const float v1 = acc[mf][nf][1];
            const float v2 = acc[mf][nf][2];
            const float v3 = acc[mf][nf][3];
            s0 += __expf(v0 - c0) + __expf(v1 - c0);
            s1 += __expf(v2 - c1) + __expf(v3 - c1);
            if (y0 == colg)     g_labelLogit[mBase + r0] = v0;
            if (y0 == colg + 1) g_labelLogit[mBase + r0] = v1;
            if (y1 == colg)     g_labelLogit[mBase + r1] = v2;
            if (y1 == colg + 1) g_labelLogit[mBase + r1] = v3;
        }
        s0 += __shfl_xor_sync(0xffffffffu, s0, 1);
        s0 += __shfl_xor_sync(0xffffffffu, s0, 2);
        s1 += __shfl_xor_sync(0xffffffffu, s1, 1);
        s1 += __shfl_xor_sync(0xffffffffu, s1, 2);
        if (quad == 0) {
            s_red[r0][wn] = s0;
            s_red[r1][wn] = s1;
        }
    }
    __syncthreads();
    if (tid < BM) {
        g_partialS[(size_t)(mBase + tid) * NVB + blockIdx.y] =
            s_red[tid][0] + s_red[tid][1] + s_red[tid][2] + s_red[tid][3];
    }
}

// ---------------------------------------------------------------------------
// Kernel 2: merge NVB partials per token -> per-token logp (masked => 0)
// ---------------------------------------------------------------------------
__global__ __launch_bounds__(128)
void lse_merge_kernel(const int* __restrict__ Y)
{
    const int token = blockIdx.x;
    const int tid   = threadIdx.x;
    __shared__ float sm[128];

    const float* pm = g_partialM + (size_t)token * NVB;
    const float* ps = g_partialS + (size_t)token * NVB;

    float mx = -3.4e38f;
    for (int i = tid; i < NVB; i += 128) mx = fmaxf(mx, pm[i]);
    sm[tid] = mx; __syncthreads();
    for (int s = 64; s > 0; s >>= 1) {
        if (tid < s) sm[tid] = fmaxf(sm[tid], sm[tid + s]);
        __syncthreads();
    }
    const float gm = sm[0];
    __syncthreads();

    float ssum = 0.0f;
    for (int i = tid; i < NVB; i += 128) ssum += ps[i] * __expf(pm[i] - gm);
    sm[tid] = ssum; __syncthreads();
    for (int s = 64; s > 0; s >>= 1) {
        if (tid < s) sm[tid] += sm[tid + s];
        __syncthreads();
    }

    if (tid == 0) {
        const float lse = gm + logf(sm[0]);
        const int yv = Y[token];
        g_logp[token] = (yv == IGNORE_INDEX) ? 0.0f : (g_labelLogit[token] - lse);
    }
}

// ---------------------------------------------------------------------------
// Kernel 3: per-sequence sums, NLL, CPO pairwise loss -> scalar
// ---------------------------------------------------------------------------
__global__ __launch_bounds__(512)
void final_kernel(const int* __restrict__ Y, float* __restrict__ out,
                  int out_size)
{
    const int tid = threadIdx.x;
    __shared__ double sm[512];
    __shared__ double allv[B2_];

    for (int s = 0; s < B2_; s++) {
        sm[tid] = (double)g_logp[s * T_SEQ + tid];
        __syncthreads();
        for (int st = 256; st > 0; st >>= 1) {
            if (tid < st) sm[tid] += sm[tid + st];
            __syncthreads();
        }
        if (tid == 0) allv[s] = sm[0];
        __syncthreads();
    }

    int c = 0;
    for (int s = 0; s < BH_; s++) c += (Y[s * T_SEQ + tid] != IGNORE_INDEX) ? 1 : 0;
    sm[tid] = (double)c;
    __syncthreads();
    for (int st = 256; st > 0; st >>= 1) {
        if (tid < st) sm[tid] += sm[tid + st];
        __syncthreads();
    }

    for (int i = tid; i < out_size; i += 512) out[i] = 0.0f;

    if (tid == 0) {
        const double cnt = sm[0];
        const double nll = -(allv[0] + allv[1] + allv[2] + allv[3]) / cnt;
        double lsum = 0.0;
        for (int b = 0; b < BH_; b++) {
            const double d = allv[b] - allv[BH_ + b];
            const double z = BETA * d;
            const double lsg = (z < 0.0) ? (z - log1p(exp(z))) : (-log1p(exp(-z)));
            lsum += -lsg;
        }
        out[0] = (float)(nll * ALPHA + lsum / (double)BH_);
    }
}

// ---------------------------------------------------------------------------
extern "C" void kernel_launch(void* const* d_in, const int* in_sizes, int n_in,
                              void* d_out, int out_size)
{
    const float* X = (const float*)d_in[0];   // (8,512,4096) f32
    const int*   Y = (const int*)d_in[1];     // (8,512) int32
    const float* W = (const float*)d_in[2];   // (32000,4096) f32

    cudaFuncSetAttribute(gemm_lse_mma,
                         cudaFuncAttributeMaxDynamicSharedMemorySize, SMEM_DYN);

    dim3 grid(NMB, NVB);   // m fastest: W slab stays hot in L2, X fits in L2
    gemm_lse_mma<<<grid, 256, SMEM_DYN>>>(X, W, Y);
    lse_merge_kernel<<<M_TOK, 128>>>(Y);
    final_kernel<<<1, 512>>>(Y, (float*)d_out, out_size);
}

// round 5
// speedup vs baseline: 15.3168x; 2.4145x over previous
#include <cuda_runtime.h>
#include <cuda_fp16.h>
#include <cstdint>

// ---------------------------------------------------------------- problem dims
#define M_TOK 4096
#define K_DIM 4096
#define V_DIM 32000
#define T_SEQ 512
#define B2_   8
#define BH_   4
#define IGNORE_INDEX (-100)
#define BETA  0.1
#define ALPHA 1.0

// ---------------------------------------------------------------- GEMM tiling
#define BM 128
#define BN 128
#define BKH 64                      // K per chunk, halfs
#define NCHUNK (K_DIM / BKH)        // 64
#define NVB (V_DIM / BN)            // 250
#define NMB (M_TOK / BM)            // 32
#define NSTAGE 3
#define A_BYTES (BM * BKH * 2)      // 16384
#define STAGE_BYTES (2 * A_BYTES)   // A + B = 32768
#define SMEM_DYN (NSTAGE * STAGE_BYTES)  // 98304

// ---------------------------------------------------------------- scratch
__device__ __align__(16) __half g_Wh[(size_t)V_DIM * K_DIM];   // 262 MB
__device__ __align__(16) __half g_Xh[(size_t)M_TOK * K_DIM];   // 33.5 MB
__device__ float g_partialM[(size_t)M_TOK * NVB];
__device__ float g_partialS[(size_t)M_TOK * NVB];
__device__ float g_labelLogit[M_TOK];
__device__ float g_logp[M_TOK];

// ---------------------------------------------------------------- helpers
__device__ __forceinline__ uint32_t smem_u32(const void* p) {
    return (uint32_t)__cvta_generic_to_shared(p);
}
__device__ __forceinline__ void cp16(uint32_t dst, const void* src) {
    asm volatile("cp.async.cg.shared.global [%0], [%1], 16;\n" :: "r"(dst), "l"(src));
}
__device__ __forceinline__ void cp_commit() {
    asm volatile("cp.async.commit_group;\n" ::: "memory");
}
template<int N> __device__ __forceinline__ void cp_wait() {
    asm volatile("cp.async.wait_group %0;\n" :: "n"(N) : "memory");
}
__device__ __forceinline__ void ldsm_x4(uint32_t& r0, uint32_t& r1,
                                        uint32_t& r2, uint32_t& r3, uint32_t a) {
    asm volatile("ldmatrix.sync.aligned.m8n8.x4.shared.b16 {%0,%1,%2,%3}, [%4];"
                 : "=r"(r0), "=r"(r1), "=r"(r2), "=r"(r3) : "r"(a));
}
__device__ __forceinline__ void mma_f16(float* c, const uint32_t* a, const uint32_t* b) {
    asm volatile(
        "mma.sync.aligned.m16n8k16.row.col.f32.f16.f16.f32 "
        "{%0,%1,%2,%3}, {%4,%5,%6,%7}, {%8,%9}, {%0,%1,%2,%3};"
        : "+f"(c[0]), "+f"(c[1]), "+f"(c[2]), "+f"(c[3])
        : "r"(a[0]), "r"(a[1]), "r"(a[2]), "r"(a[3]), "r"(b[0]), "r"(b[1]));
}

// ---------------------------------------------------------------------------
// Kernel 0: fp32 -> fp16 conversion (X and W)
// ---------------------------------------------------------------------------
__global__ __launch_bounds__(256)
void convert_kernel(const float4* __restrict__ src, __half2* __restrict__ dst,
                    int n4)
{
    const int i = blockIdx.x * 256 + threadIdx.x;
    if (i < n4) {
        const float4 v = src[i];
        dst[2 * i + 0] = __floats2half2_rn(v.x, v.y);
        dst[2 * i + 1] = __floats2half2_rn(v.z, v.w);
    }
}

// ---------------------------------------------------------------------------
// Kernel 1: fp16 mma.sync GEMM (128x128 tile, BK=64) + fused logsumexp
// partials + label gather. grid=(32,250), 256 threads (8 warps, 2x4).
// smem layout per stage: A [128 rows][8 units of 16B], unit swizzled by row&7.
// ---------------------------------------------------------------------------
__global__ void __launch_bounds__(256, 2)
gemm_lse_mma(const __half* __restrict__ Xh, const __half* __restrict__ Wh,
             const int* __restrict__ Y)
{
    extern __shared__ char smem[];
    __shared__ float s_red[BM][5];
    __shared__ float s_rowmax[BM];

    const int tid   = threadIdx.x;
    const int lane  = tid & 31;
    const int wid   = tid >> 5;
    const int wm    = wid & 1;      // 0..1 -> 64-row half
    const int wn    = wid >> 1;     // 0..3 -> 32-col group
    const int quad  = lane & 3;
    const int l4    = lane >> 2;
    const int mBase = blockIdx.x * BM;
    const int nBase = blockIdx.y * BN;

    const uint32_t s_base = smem_u32(smem);

    // ---- per-lane ldmatrix address components (constant across chunks) ----
    // A: lanes 0-7: rows m0+(l&7), unit 2ks ; 8-15: rows +8 ; 16-23: rows, unit
    // 2ks+1 ; 24-31: rows+8, unit 2ks+1
    int aRow[4], aRowSw[4];
#pragma unroll
    for (int mf = 0; mf < 4; mf++) {
        aRow[mf]   = wm * 64 + mf * 16 + (lane & 7) + ((lane >> 3) & 1) * 8;
        aRowSw[mf] = aRow[mf] & 7;
    }
    const int aUhi = (lane >> 4) & 1;
    // B: lanes 0-7: n0+(l&7), unit 2ks ; 8-15: n0.., unit 2ks+1 ; 16-23: n0+8..,
    // unit 2ks ; 24-31: n0+8.., unit 2ks+1
    int bRow[2], bRowSw[2];
#pragma unroll
    for (int g = 0; g < 2; g++) {
        bRow[g]   = wn * 32 + g * 16 + (lane & 7) + ((lane >> 4) & 1) * 8;
        bRowSw[g] = bRow[g] & 7;
    }
    const int bUhi = (lane >> 3) & 1;

    // ---- chunk loader: 128x64 halfs for A and B, 16B cp.async, swizzled ----
    auto load_chunk = [&](int j) {
        const uint32_t stB = s_base + (uint32_t)(j % NSTAGE) * STAGE_BYTES;
        const int k0 = j * BKH;
#pragma unroll
        for (int q = 0; q < 4; q++) {
            const int idx = q * 256 + tid;
            const int row = idx >> 3, u = idx & 7;
            const uint32_t off = (uint32_t)(row * 128 + ((u ^ (row & 7)) * 16));
            cp16(stB + off,           Xh + (size_t)(mBase + row) * K_DIM + k0 + u * 8);
            cp16(stB + A_BYTES + off, Wh + (size_t)(nBase + row) * K_DIM + k0 + u * 8);
        }
        cp_commit();
    };

    float acc[4][4][4];
#pragma unroll
    for (int mf = 0; mf < 4; mf++)
#pragma unroll
        for (int nf = 0; nf < 4; nf++)
#pragma unroll
            for (int r = 0; r < 4; r++) acc[mf][nf][r] = 0.0f;

    load_chunk(0);
    load_chunk(1);

    for (int i = 0; i < NCHUNK; i++) {
        if (i == NCHUNK - 1) cp_wait<0>(); else cp_wait<1>();
        __syncthreads();

        const uint32_t stA = s_base + (uint32_t)(i % NSTAGE) * STAGE_BYTES;
        const uint32_t stBB = stA + A_BYTES;

#pragma unroll
        for (int ks = 0; ks < 4; ks++) {   // 4 x k16 per 64-half chunk
            uint32_t a[4][4], b[4][2];
#pragma unroll
            for (int mf = 0; mf < 4; mf++) {
                const int u = (2 * ks + aUhi) ^ aRowSw[mf];
                ldsm_x4(a[mf][0], a[mf][1], a[mf][2], a[mf][3],
                        stA + (uint32_t)(aRow[mf] * 128 + u * 16));
            }
#pragma unroll
            for (int g = 0; g < 2; g++) {
                const int u = (2 * ks + bUhi) ^ bRowSw[g];
                ldsm_x4(b[2 * g][0], b[2 * g][1], b[2 * g + 1][0], b[2 * g + 1][1],
                        stBB + (uint32_t)(bRow[g] * 128 + u * 16));
            }
#pragma unroll
            for (int mf = 0; mf < 4; mf++)
#pragma unroll
                for (int nf = 0; nf < 4; nf++)
                    mma_f16(acc[mf][nf], a[mf], b[nf]);
        }
        // write stage (i+2)%3: its last readers (chunk i-1) all passed the
        // barrier at the top of this iteration -> safe with ONE barrier/iter.
        if (i + 2 < NCHUNK) load_chunk(i + 2);
    }

    // --------------------------- epilogue ----------------------------------
#pragma unroll
    for (int mf = 0; mf < 4; mf++) {
        float m0 = -3.4e38f, m1 = -3.4e38f;
#pragma unroll
        for (int nf = 0; nf < 4; nf++) {
            m0 = fmaxf(m0, fmaxf(acc[mf][nf][0], acc[mf][nf][1]));
            m1 = fmaxf(m1, fmaxf(acc[mf][nf][2], acc[mf][nf][3]));
        }
        m0 = fmaxf(m0, __shfl_xor_sync(0xffffffffu, m0, 1));
        m0 = fmaxf(m0, __shfl_xor_sync(0xffffffffu, m0, 2));
        m1 = fmaxf(m1, __shfl_xor_sync(0xffffffffu, m1, 1));
        m1 = fmaxf(m1, __shfl_xor_sync(0xffffffffu, m1, 2));
        if (quad == 0) {
            s_red[wm * 64 + mf * 16 + l4][wn]     = m0;
            s_red[wm * 64 + mf * 16 + l4 + 8][wn] = m1;
        }
    }
    __syncthreads();
    if (tid < BM) {
        const float rm = fmaxf(fmaxf(s_red[tid][0], s_red[tid][1]),
                               fmaxf(s_red[tid][2], s_red[tid][3]));
        s_rowmax[tid] = rm;
        g_partialM[(size_t)(mBase + tid) * NVB + blockIdx.y] = rm;
    }
    __syncthreads();

#pragma unroll
    for (int mf = 0; mf < 4; mf++) {
        const int r0 = wm * 64 + mf * 16 + l4;
        const int r1 = r0 + 8;
        const float c0 = s_rowmax[r0];
        const float c1 = s_rowmax[r1];
        const int y0 = Y[mBase + r0];
        const int y1 = Y[mBase + r1];
        float s0 = 0.0f, s1 = 0.0f;
#pragma unroll
        for (int nf = 0; nf < 4; nf++) {
            const int colg = nBase + wn * 32 + nf * 8 + 2 * quad;
            const float v0 = acc[mf][nf][0];
            const float v1 = acc[mf][nf][1];
            const float v2 = acc[mf][nf][2];
            const float v3 = acc[mf][nf][3];
            s0 += __expf(v0 - c0) + __expf(v1 - c0);
            s1 += __expf(v2 - c1) + __expf(v3 - c1);
            if (y0 == colg)     g_labelLogit[mBase + r0] = v0;
            if (y0 == colg + 1) g_labelLogit[mBase + r0] = v1;
            if (y1 == colg)     g_labelLogit[mBase + r1] = v2;
            if (y1 == colg + 1) g_labelLogit[mBase + r1] = v3;
        }
        s0 += __shfl_xor_sync(0xffffffffu, s0, 1);
        s0 += __shfl_xor_sync(0xffffffffu, s0, 2);
        s1 += __shfl_xor_sync(0xffffffffu, s1, 1);
        s1 += __shfl_xor_sync(0xffffffffu, s1, 2);
        if (quad == 0) {
            s_red[r0][wn] = s0;
            s_red[r1][wn] = s1;
        }
    }
    __syncthreads();
    if (tid < BM) {
        g_partialS[(size_t)(mBase + tid) * NVB + blockIdx.y] =
            s_red[tid][0] + s_red[tid][1] + s_red[tid][2] + s_red[tid][3];
    }
}

// ---------------------------------------------------------------------------
// Kernel 2: merge NVB partials per token -> per-token logp (masked => 0)
// ---------------------------------------------------------------------------
__global__ __launch_bounds__(128)
void lse_merge_kernel(const int* __restrict__ Y)
{
    const int token = blockIdx.x;
    const int tid   = threadIdx.x;
    __shared__ float sm[128];

    const float* pm = g_partialM + (size_t)token * NVB;
    const float* ps = g_partialS + (size_t)token * NVB;

    float mx = -3.4e38f;
    for (int i = tid; i < NVB; i += 128) mx = fmaxf(mx, pm[i]);
    sm[tid] = mx; __syncthreads();
    for (int s = 64; s > 0; s >>= 1) {
        if (tid < s) sm[tid] = fmaxf(sm[tid], sm[tid + s]);
        __syncthreads();
    }
    const float gm = sm[0];
    __syncthreads();

    float ssum = 0.0f;
    for (int i = tid; i < NVB; i += 128) ssum += ps[i] * __expf(pm[i] - gm);
    sm[tid] = ssum; __syncthreads();
    for (int s = 64; s > 0; s >>= 1) {
        if (tid < s) sm[tid] += sm[tid + s];
        __syncthreads();
    }

    if (tid == 0) {
        const float lse = gm + logf(sm[0]);
        const int yv = Y[token];
        g_logp[token] = (yv == IGNORE_INDEX) ? 0.0f : (g_labelLogit[token] - lse);
    }
}

// ---------------------------------------------------------------------------
// Kernel 3: per-sequence sums, NLL, CPO pairwise loss -> scalar
// ---------------------------------------------------------------------------
__global__ __launch_bounds__(512)
void final_kernel(const int* __restrict__ Y, float* __restrict__ out,
                  int out_size)
{
    const int tid = threadIdx.x;
    __shared__ double sm[512];
    __shared__ double allv[B2_];

    for (int s = 0; s < B2_; s++) {
        sm[tid] = (double)g_logp[s * T_SEQ + tid];
        __syncthreads();
        for (int st = 256; st > 0; st >>= 1) {
            if (tid < st) sm[tid] += sm[tid + st];
            __syncthreads();
        }
        if (tid == 0) allv[s] = sm[0];
        __syncthreads();
    }

    int c = 0;
    for (int s = 0; s < BH_; s++) c += (Y[s * T_SEQ + tid] != IGNORE_INDEX) ? 1 : 0;
    sm[tid] = (double)c;
    __syncthreads();
    for (int st = 256; st > 0; st >>= 1) {
        if (tid < st) sm[tid] += sm[tid + st];
        __syncthreads();
    }

    for (int i = tid; i < out_size; i += 512) out[i] = 0.0f;

    if (tid == 0) {
        const double cnt = sm[0];
        const double nll = -(allv[0] + allv[1] + allv[2] + allv[3]) / cnt;
        double lsum = 0.0;
        for (int b = 0; b < BH_; b++) {
            const double d = allv[b] - allv[BH_ + b];
            const double z = BETA * d;
            const double lsg = (z < 0.0) ? (z - log1p(exp(z))) : (-log1p(exp(-z)));
            lsum += -lsg;
        }
        out[0] = (float)(nll * ALPHA + lsum / (double)BH_);
    }
}

// ---------------------------------------------------------------------------
extern "C" void kernel_launch(void* const* d_in, const int* in_sizes, int n_in,
                              void* d_out, int out_size)
{
    const float* X = (const float*)d_in[0];   // (8,512,4096) f32
    const int*   Y = (const int*)d_in[1];     // (8,512) int32
    const float* W = (const float*)d_in[2];   // (32000,4096) f32

    __half* Xh; cudaGetSymbolAddress((void**)&Xh, g_Xh);
    __half* Wh; cudaGetSymbolAddress((void**)&Wh, g_Wh);

    // fp32 -> fp16 pre-conversion
    const int nx4 = (M_TOK * K_DIM) / 4;          // 4,194,304
    const int nw4 = (V_DIM * K_DIM) / 4;          // 32,768,000
    convert_kernel<<<(nx4 + 255) / 256, 256>>>((const float4*)X, (__half2*)Xh, nx4);
    convert_kernel<<<(nw4 + 255) / 256, 256>>>((const float4*)W, (__half2*)Wh, nw4);

    cudaFuncSetAttribute(gemm_lse_mma,
                         cudaFuncAttributeMaxDynamicSharedMemorySize, SMEM_DYN);

    dim3 grid(NMB, NVB);   // m fastest: W slab hot in L2, X L2-resident
    gemm_lse_mma<<<grid, 256, SMEM_DYN>>>(Xh, Wh, Y);
    lse_merge_kernel<<<M_TOK, 128>>>(Y);
    final_kernel<<<1, 512>>>(Y, (float*)d_out, out_size);
}